// round 14
// baseline (speedup 1.0000x reference)
#include <cuda_runtime.h>
#include <cuda_bf16.h>
#include <cstdint>

// Problem constants (fixed by the dataset): input [B, C, T] fp32
#define B_DIM 16
#define C_DIM 256
#define T_DIM 16000
#define EPS 1e-8f

#define TPB 256
#define T_PER_BLK 1024                 // 256 threads x 4 t (float4)
#define NCHUNK ((T_DIM + T_PER_BLK - 1) / T_PER_BLK)   // 16
#define C_SPLIT 4                      // K1: channel splits
#define CPS (C_DIM / C_SPLIT)          // 64 channels per split

#define K3_CSPLIT 4                    // K3: channel slices per (b, chunk)
#define K3_CPS (C_DIM / K3_CSPLIT)     // 64 channels per block

#define OCT 8                          // scan octants per batch
#define OCT_T (T_DIM / OCT)            // 2000 timesteps per octant

#define NGRP 4                         // batch pipeline groups
#define BPG (B_DIM / NGRP)             // 4 batches per group

// scratch (device globals; allocation is forbidden)
__device__ float2 g_part[C_SPLIT * B_DIM * T_DIM]; // partial (sum,sumsq)  8 MB
__device__ float2 g_scan[B_DIM * T_DIM];           // octant-local inclusive (S,P) 2 MB
__device__ float2 g_agg [B_DIM * OCT];             // octant aggregates
__device__ float2 g_off [B_DIM * OCT];             // octant exclusive offsets
__device__ int    g_cnt [NGRP];                    // per-group last-block counters

// ---------------- K1: partial channel reduction (pure streaming) ----------------
__global__ __launch_bounds__(TPB) void colsum_kernel(const float* __restrict__ x,
                                                     int batch_base)
{
    const int cs = blockIdx.y;          // channel split 0..3
    const int b  = batch_base + blockIdx.z;
    const int t4 = blockIdx.x * T_PER_BLK + threadIdx.x * 4;
    if (t4 >= T_DIM) return;            // 640 % 4 == 0: thread fully valid or not

    const float* px = x + ((size_t)b * C_DIM + cs * CPS) * T_DIM + t4;

    float4 s = make_float4(0.f, 0.f, 0.f, 0.f);
    float4 p = make_float4(0.f, 0.f, 0.f, 0.f);
    #pragma unroll 8
    for (int c = 0; c < CPS; c++) {
        const float4 v = __ldcs((const float4*)(px + (size_t)c * T_DIM));
        s.x += v.x; s.y += v.y; s.z += v.z; s.w += v.w;
        p.x = fmaf(v.x, v.x, p.x); p.y = fmaf(v.y, v.y, p.y);
        p.z = fmaf(v.z, v.z, p.z); p.w = fmaf(v.w, v.w, p.w);
    }

    float2* dst = g_part + ((size_t)cs * B_DIM + b) * T_DIM + t4;
    ((float4*)dst)[0] = make_float4(s.x, p.x, s.y, p.y);
    ((float4*)dst)[1] = make_float4(s.z, p.z, s.w, p.w);
}

// ------- K2: octant-parallel combine+scan (32 blocks/group) + fused 2nd level -------
#define SCAN_TPB 1024

__global__ __launch_bounds__(SCAN_TPB) void scan2_kernel(int batch_base, int grp)
{
    __shared__ float2 sm[OCT_T];                     // 16 KB local (S,P)
    __shared__ float  swS[32], swP[32];
    __shared__ int    s_last;

    const int o    = blockIdx.x;                     // octant 0..7
    const int b    = batch_base + blockIdx.y;        // global batch
    const int tid  = threadIdx.x;
    const int lane = tid & 31;
    const int wid  = tid >> 5;

    const float4* p4   = (const float4*)g_part;      // {S0,P0,S1,P1} per pair
    const size_t  strm = (size_t)B_DIM * T_DIM / 2;  // float4s per cs stream
    const size_t  base4 = (size_t)b * (T_DIM / 2) + (size_t)o * (OCT_T / 2);

#if __CUDA_ARCH__ >= 900
    cudaGridDependencySynchronize();                 // wait for this group's colsum
#endif

    // ---- Phase A: coalesced combine of 4 partial streams into smem ----
    if (tid < OCT_T / 2) {                           // 1000 active threads
        float4 a0 = p4[base4 + tid];
        const float4 a1 = p4[strm + base4 + tid];
        const float4 a2 = p4[2 * strm + base4 + tid];
        const float4 a3 = p4[3 * strm + base4 + tid];
        a0.x += a1.x + a2.x + a3.x;  a0.y += a1.y + a2.y + a3.y;
        a0.z += a1.z + a2.z + a3.z;  a0.w += a1.w + a2.w + a3.w;
        sm[2 * tid]     = make_float2(a0.x, a0.y);
        sm[2 * tid + 1] = make_float2(a0.z, a0.w);
    }
    __syncthreads();

    // ---- Phase B: local scan (EPT=2) ----
    const int  i0    = tid * 2;
    const bool valid = (i0 < OCT_T);
    float s0 = 0.f, p0 = 0.f, s1 = 0.f, p1 = 0.f;
    if (valid) {
        const float2 a = sm[i0];
        const float2 c = sm[i0 + 1];
        s0 = a.x; p0 = a.y;
        s1 = s0 + c.x; p1 = p0 + c.y;
    }
    float iS = s1, iP = p1;                          // thread-inclusive totals
    #pragma unroll
    for (int off = 1; off < 32; off <<= 1) {
        float nS = __shfl_up_sync(0xffffffffu, iS, off);
        float nP = __shfl_up_sync(0xffffffffu, iP, off);
        if (lane >= off) { iS += nS; iP += nP; }
    }
    if (lane == 31) { swS[wid] = iS; swP[wid] = iP; }
    __syncthreads();
    if (wid == 0) {
        float wS = swS[lane], wP = swP[lane];
        #pragma unroll
        for (int off = 1; off < 32; off <<= 1) {
            float nS = __shfl_up_sync(0xffffffffu, wS, off);
            float nP = __shfl_up_sync(0xffffffffu, wP, off);
            if (lane >= off) { wS += nS; wP += nP; }
        }
        swS[lane] = wS - swS[lane];                  // exclusive warp offsets
        swP[lane] = wP - swP[lane];
    }
    __syncthreads();
    const float excS = swS[wid] + (iS - s1);         // thread-exclusive prefix
    const float excP = swP[wid] + (iP - p1);

    // ---- write octant-local inclusive scan (coalesced float4) ----
    if (valid) {
        ((float4*)g_scan)[base4 + tid] =
            make_float4(excS + s0, excP + p0, excS + s1, excP + p1);
    }

    // ---- publish octant aggregate; last block of the GROUP does 2nd level ----
    if (tid == OCT_T / 2 - 1) {                      // owns the octant total
        g_agg[b * OCT + o] = make_float2(excS + s1, excP + p1);
        __threadfence();
        const int old = atomicAdd(&g_cnt[grp], 1);
        s_last = (old == OCT * BPG - 1) ? 1 : 0;
    }
    __syncthreads();

    if (s_last) {
        __threadfence();                             // acquire: see all group g_agg
        if (tid < BPG) {
            const int bb = batch_base + tid;
            float aS = 0.f, aP = 0.f;
            #pragma unroll
            for (int o2 = 0; o2 < OCT; o2++) {
                g_off[bb * OCT + o2] = make_float2(aS, aP);
                const float2 a = g_agg[bb * OCT + o2];
                aS += a.x; aP += a.y;
            }
        }
        __syncthreads();
        if (tid == 0) { __threadfence(); g_cnt[grp] = 0; }  // reset for next replay
    }
}

// ------- K3: normalize; local scan + octant offset -> stats computed inline -------
__global__ __launch_bounds__(TPB) void norm_kernel(
    const float* __restrict__ x,
    const float* __restrict__ gain,
    const float* __restrict__ bias,
    float* __restrict__ out,
    int batch_base)
{
    __shared__ float s_gain[K3_CPS];
    __shared__ float s_bias[K3_CPS];

    const int cs = blockIdx.y;          // channel slice 0..3
    const int b  = batch_base + blockIdx.z;
    const int c0 = cs * K3_CPS;

    // independent of the scan: run before the dependency sync
    if (threadIdx.x < K3_CPS) {
        s_gain[threadIdx.x] = gain[c0 + threadIdx.x];
        s_bias[threadIdx.x] = bias[c0 + threadIdx.x];
    }
    __syncthreads();

    const int t4 = blockIdx.x * T_PER_BLK + threadIdx.x * 4;
    if (t4 >= T_DIM) return;

    const size_t base = ((size_t)b * C_DIM + c0) * T_DIM + t4;
    const float* px = x   + base;
    float*       po = out + base;

#if __CUDA_ARCH__ >= 900
    cudaGridDependencySynchronize();    // wait for this group's scan
#endif

    // octant offset (OCT_T multiple of 4 -> whole float4 in one octant)
    const float2 off = g_off[b * OCT + t4 / OCT_T];
    const float4* sp = (const float4*)(g_scan + (size_t)b * T_DIM + t4);
    const float4 l01 = sp[0];           // {S0,P0,S1,P1} local inclusive
    const float4 l23 = sp[1];

    float mean[4], inv[4];
    {
        const float S[4] = { l01.x, l01.z, l23.x, l23.z };
        const float P[4] = { l01.y, l01.w, l23.y, l23.w };
        #pragma unroll
        for (int j = 0; j < 4; j++) {
            const float cnt  = (float)(t4 + 1 + j) * (float)C_DIM;
            const float rc   = __fdividef(1.0f, cnt);
            const float m    = (off.x + S[j]) * rc;
            mean[j] = m;
            inv[j]  = rsqrtf((off.y + P[j]) * rc - m * m + EPS);
        }
    }

    #pragma unroll 8
    for (int c = 0; c < K3_CPS; c++) {
        const float g  = s_gain[c];
        const float bi = s_bias[c];
        const float4 v = __ldcs((const float4*)(px + (size_t)c * T_DIM));
        float4 o;
        o.x = fmaf((v.x - mean[0]) * inv[0], g, bi);
        o.y = fmaf((v.y - mean[1]) * inv[1], g, bi);
        o.z = fmaf((v.z - mean[2]) * inv[2], g, bi);
        o.w = fmaf((v.w - mean[3]) * inv[3], g, bi);
        __stcs((float4*)(po + (size_t)c * T_DIM), o);
    }
}

// ---- PDL launch helper ----
static inline void pdl_launch_colsum(const float* x, int batch_base, bool pdl)
{
    cudaLaunchAttribute attr[1];
    attr[0].id = cudaLaunchAttributeProgrammaticStreamSerialization;
    attr[0].val.programmaticStreamSerializationAllowed = 1;
    cudaLaunchConfig_t cfg = {};
    cfg.gridDim = dim3(NCHUNK, C_SPLIT, BPG);
    cfg.blockDim = dim3(TPB);
    cfg.stream = 0;
    cfg.attrs = attr;
    cfg.numAttrs = pdl ? 1 : 0;
    cudaLaunchKernelEx(&cfg, colsum_kernel, x, batch_base);
}

extern "C" void kernel_launch(void* const* d_in, const int* in_sizes, int n_in,
                              void* d_out, int out_size)
{
    const float* x    = (const float*)d_in[0];
    const float* gain = (const float*)d_in[1];
    const float* bias = (const float*)d_in[2];
    float* out = (float*)d_out;

    for (int g = 0; g < NGRP; g++) {
        const int bb = g * BPG;

        // K1(g): PDL attr (overlaps K3(g-1)); never syncs — no data dependency
        pdl_launch_colsum(x, bb, g > 0);

        // scan(g): PDL; syncs on K1(g)
        {
            cudaLaunchAttribute attr[1];
            attr[0].id = cudaLaunchAttributeProgrammaticStreamSerialization;
            attr[0].val.programmaticStreamSerializationAllowed = 1;
            cudaLaunchConfig_t cfg = {};
            cfg.gridDim = dim3(OCT, BPG);
            cfg.blockDim = dim3(SCAN_TPB);
            cfg.stream = 0;
            cfg.attrs = attr;
            cfg.numAttrs = 1;
            cudaLaunchKernelEx(&cfg, scan2_kernel, bb, g);
        }

        // K3(g): PDL; syncs on scan(g)
        {
            cudaLaunchAttribute attr[1];
            attr[0].id = cudaLaunchAttributeProgrammaticStreamSerialization;
            attr[0].val.programmaticStreamSerializationAllowed = 1;
            cudaLaunchConfig_t cfg = {};
            cfg.gridDim = dim3(NCHUNK, K3_CSPLIT, BPG);
            cfg.blockDim = dim3(TPB);
            cfg.stream = 0;
            cfg.attrs = attr;
            cfg.numAttrs = 1;
            cudaLaunchKernelEx(&cfg, norm_kernel, x, gain, bias, out, bb);
        }
    }
}

// round 15
// speedup vs baseline: 1.7296x; 1.7296x over previous
#include <cuda_runtime.h>
#include <cuda_bf16.h>
#include <cstdint>

// Problem constants (fixed by the dataset): input [B, C, T] fp32
#define B_DIM 16
#define C_DIM 256
#define T_DIM 16000
#define EPS 1e-8f

#define TPB 256
#define T_PER_BLK 1024                 // 256 threads x 4 t (float4)
#define NCHUNK ((T_DIM + T_PER_BLK - 1) / T_PER_BLK)   // 16
#define C_SPLIT 4                      // channel splits (64 channels per block)
#define CPS (C_DIM / C_SPLIT)          // 64

#define OCT 8                          // scan octants per batch
#define OCT_T (T_DIM / OCT)            // 2000 timesteps per octant
#define SCAN_BLOCKS (B_DIM * OCT)      // 128

#define GRID_TOTAL (NCHUNK * C_SPLIT * B_DIM)   // 1024 blocks — all co-resident @8/SM

#define SKEW(i) ((i) + ((i) >> 4))

// scratch (device globals; allocation is forbidden)
__device__ float2 g_part[C_SPLIT * B_DIM * T_DIM]; // partial (sum,sumsq)  8 MB
__device__ float2 g_scan[B_DIM * T_DIM];           // octant-local inclusive (S,P) 2 MB
__device__ float2 g_agg [B_DIM * OCT];             // octant aggregates (2 KB)
__device__ int    bar_cnt;                         // barrier counter (self-resetting)
__device__ volatile int bar_sense;                 // barrier sense (returns to 0)

// Sense-reversal grid barrier. Safe: all GRID_TOTAL blocks are co-resident
// (1024 <= 8 blocks/SM * 148 SMs), enforced by __launch_bounds__(256, 8).
__device__ __forceinline__ void grid_barrier(int& local_sense)
{
    __syncthreads();
    if (threadIdx.x == 0) {
        const int s = local_sense ^ 1;
        local_sense = s;
        __threadfence();                             // release phase writes
        if (atomicAdd(&bar_cnt, 1) == GRID_TOTAL - 1) {
            bar_cnt = 0;                             // reset BEFORE release
            __threadfence();
            bar_sense = s;                           // release all
        } else {
            while (bar_sense != s) { __nanosleep(64); }
        }
        __threadfence();                             // acquire others' writes
    }
    __syncthreads();
}

__global__ __launch_bounds__(TPB, 8) void cln_fused_kernel(
    const float* __restrict__ x,
    const float* __restrict__ gain,
    const float* __restrict__ bias,
    float* __restrict__ out)
{
    __shared__ float2 sm[OCT_T + OCT_T / 16];        // scan staging (skewed), ~16.9 KB
    __shared__ float  swS[8], swP[8];

    const int tid   = threadIdx.x;
    const int flat  = blockIdx.x;
    const int chunk = flat % NCHUNK;
    const int cs    = (flat / NCHUNK) % C_SPLIT;
    const int b     = flat / (NCHUNK * C_SPLIT);
    int sense = 0;

    const int  t4    = chunk * T_PER_BLK + tid * 4;
    const bool valid = (t4 < T_DIM);

    const size_t xbase = ((size_t)b * C_DIM + cs * CPS) * T_DIM + t4;

    // ================= Phase 1: partial channel reduction =================
    if (valid) {
        const float* px = x + xbase;
        float4 s = make_float4(0.f, 0.f, 0.f, 0.f);
        float4 p = make_float4(0.f, 0.f, 0.f, 0.f);
        #pragma unroll 8
        for (int c = 0; c < CPS; c++) {
            const float4 v = __ldcs((const float4*)(px + (size_t)c * T_DIM));
            s.x += v.x; s.y += v.y; s.z += v.z; s.w += v.w;
            p.x = fmaf(v.x, v.x, p.x); p.y = fmaf(v.y, v.y, p.y);
            p.z = fmaf(v.z, v.z, p.z); p.w = fmaf(v.w, v.w, p.w);
        }
        float2* dst = g_part + ((size_t)cs * B_DIM + b) * T_DIM + t4;
        ((float4*)dst)[0] = make_float4(s.x, p.x, s.y, p.y);   // stays L2-resident
        ((float4*)dst)[1] = make_float4(s.z, p.z, s.w, p.w);
    }

    grid_barrier(sense);

    // ================= Phase 2: octant scans (first 128 blocks) =================
    if (flat < SCAN_BLOCKS) {
        const int o  = flat & (OCT - 1);
        const int b2 = flat >> 3;
        const int lane = tid & 31;
        const int wid  = tid >> 5;

        const float4* p4   = (const float4*)g_part;
        const size_t  strm = (size_t)B_DIM * T_DIM / 2;
        const size_t  base4 = (size_t)b2 * (T_DIM / 2) + (size_t)o * (OCT_T / 2);

        // combine 4 partial streams (coalesced float4, mostly L2 hits)
        for (int i2 = tid; i2 < OCT_T / 2; i2 += TPB) {
            float4 a0 = p4[base4 + i2];
            const float4 a1 = p4[strm + base4 + i2];
            const float4 a2 = p4[2 * strm + base4 + i2];
            const float4 a3 = p4[3 * strm + base4 + i2];
            a0.x += a1.x + a2.x + a3.x;  a0.y += a1.y + a2.y + a3.y;
            a0.z += a1.z + a2.z + a3.z;  a0.w += a1.w + a2.w + a3.w;
            const int i = i2 * 2;
            sm[SKEW(i)]     = make_float2(a0.x, a0.y);
            sm[SKEW(i + 1)] = make_float2(a0.z, a0.w);
        }
        __syncthreads();

        // blocked local scan, EPT=8 (250 active threads)
        const int start = tid * 8;
        float vs[8], vp[8];
        #pragma unroll
        for (int j = 0; j < 8; j++) {
            const int i = start + j;
            const float2 v = (i < OCT_T) ? sm[SKEW(i)] : make_float2(0.f, 0.f);
            vs[j] = v.x; vp[j] = v.y;
        }
        #pragma unroll
        for (int j = 1; j < 8; j++) { vs[j] += vs[j - 1]; vp[j] += vp[j - 1]; }

        float tS = vs[7], tP = vp[7];
        float iS = tS, iP = tP;
        #pragma unroll
        for (int off = 1; off < 32; off <<= 1) {
            float nS = __shfl_up_sync(0xffffffffu, iS, off);
            float nP = __shfl_up_sync(0xffffffffu, iP, off);
            if (lane >= off) { iS += nS; iP += nP; }
        }
        if (lane == 31) { swS[wid] = iS; swP[wid] = iP; }
        __syncthreads();
        if (wid == 0 && lane < 8) {
            float wS = swS[lane], wP = swP[lane];
            #pragma unroll
            for (int off = 1; off < 8; off <<= 1) {
                float nS = __shfl_up_sync(0xffu, wS, off);
                float nP = __shfl_up_sync(0xffu, wP, off);
                if (lane >= off) { wS += nS; wP += nP; }
            }
            swS[lane] = wS - swS[lane];              // exclusive warp offsets
            swP[lane] = wP - swP[lane];
        }
        __syncthreads();
        const float excS = swS[wid] + (iS - tS);
        const float excP = swP[wid] + (iP - tP);

        // write octant-local inclusive scan (float4 = 2 timesteps)
        if (start < OCT_T) {
            float4* sc4 = (float4*)g_scan;
            #pragma unroll
            for (int k = 0; k < 4; k++) {
                sc4[base4 + start / 2 + k] =
                    make_float4(excS + vs[2 * k],     excP + vp[2 * k],
                                excS + vs[2 * k + 1], excP + vp[2 * k + 1]);
            }
            if (start + 8 == OCT_T)                  // tid 249 owns the octant total
                g_agg[b2 * OCT + o] = make_float2(excS + vs[7], excP + vp[7]);
        }
    }

    grid_barrier(sense);

    // ================= Phase 3: normalize =================
    if (valid) {
        // octant offset folded inline (g_agg is 2 KB -> L1-hot)
        const int oct = t4 / OCT_T;
        float offS = 0.f, offP = 0.f;
        for (int o2 = 0; o2 < oct; o2++) {
            const float2 a = __ldg(&g_agg[b * OCT + o2]);
            offS += a.x; offP += a.y;
        }

        const float4* sp = (const float4*)(g_scan + (size_t)b * T_DIM + t4);
        const float4 l01 = sp[0];
        const float4 l23 = sp[1];

        float mean[4], inv[4];
        {
            const float S[4] = { l01.x, l01.z, l23.x, l23.z };
            const float P[4] = { l01.y, l01.w, l23.y, l23.w };
            #pragma unroll
            for (int j = 0; j < 4; j++) {
                const float cnt = (float)(t4 + 1 + j) * (float)C_DIM;
                const float rc  = __fdividef(1.0f, cnt);
                const float m   = (offS + S[j]) * rc;
                mean[j] = m;
                inv[j]  = rsqrtf((offP + P[j]) * rc - m * m + EPS);
            }
        }

        const int c0 = cs * CPS;
        const float* px = x   + xbase;
        float*       po = out + xbase;
        #pragma unroll 8
        for (int c = 0; c < CPS; c++) {
            const float g  = __ldg(gain + c0 + c);
            const float bi = __ldg(bias + c0 + c);
            const float4 v = __ldcs((const float4*)(px + (size_t)c * T_DIM));
            float4 o;
            o.x = fmaf((v.x - mean[0]) * inv[0], g, bi);
            o.y = fmaf((v.y - mean[1]) * inv[1], g, bi);
            o.z = fmaf((v.z - mean[2]) * inv[2], g, bi);
            o.w = fmaf((v.w - mean[3]) * inv[3], g, bi);
            __stcs((float4*)(po + (size_t)c * T_DIM), o);
        }
    }
}

extern "C" void kernel_launch(void* const* d_in, const int* in_sizes, int n_in,
                              void* d_out, int out_size)
{
    const float* x    = (const float*)d_in[0];
    const float* gain = (const float*)d_in[1];
    const float* bias = (const float*)d_in[2];
    float* out = (float*)d_out;

    cln_fused_kernel<<<GRID_TOTAL, TPB>>>(x, gain, bias, out);
}

// round 16
// speedup vs baseline: 1.7390x; 1.0054x over previous
#include <cuda_runtime.h>
#include <cuda_bf16.h>
#include <cstdint>

// Problem constants (fixed by the dataset): input [B, C, T] fp32
#define B_DIM 16
#define C_DIM 256
#define T_DIM 16000
#define EPS 1e-8f

#define TPB 256
#define T_PER_BLK 1024                 // 256 threads x 4 t (float4)
#define NCHUNK ((T_DIM + T_PER_BLK - 1) / T_PER_BLK)   // 16
#define C_SPLIT 4                      // channel splits (64 channels per block)
#define CPS (C_DIM / C_SPLIT)          // 64
#define BLK_PER_B (NCHUNK * C_SPLIT)   // 64 blocks per batch

#define OCT 8                          // scan octants per batch
#define OCT_T (T_DIM / OCT)            // 2000 timesteps per octant

#define GRID_TOTAL (BLK_PER_B * B_DIM) // 1024 blocks — all co-resident @8/SM

#define SKEW(i) ((i) + ((i) >> 4))

// scratch (device globals; allocation is forbidden)
__device__ float2 g_part[C_SPLIT * B_DIM * T_DIM]; // partial (sum,sumsq)  8 MB
__device__ float2 g_scan[B_DIM * T_DIM];           // octant-local inclusive (S,P) 2 MB
__device__ float2 g_agg [B_DIM * OCT];             // octant aggregates (2 KB)
__device__ int    done1[B_DIM];                    // phase-1 arrivals (target 64)
__device__ int    done2[B_DIM];                    // scan arrivals   (target 8)
__device__ int    done3[B_DIM];                    // finish arrivals (target 64) -> reset

__device__ __forceinline__ void wait_counter(volatile int* cnt, int target)
{
    // called by tid 0 only
    while (*cnt < target) { __nanosleep(64); }
    __threadfence();                                 // acquire producers' writes
}

__global__ __launch_bounds__(TPB, 8) void cln_fused_kernel(
    const float* __restrict__ x,
    const float* __restrict__ gain,
    const float* __restrict__ bias,
    float* __restrict__ out)
{
    __shared__ float2 sm[OCT_T + OCT_T / 16];        // scan staging (skewed), ~16.9 KB
    __shared__ float  swS[8], swP[8];

    const int tid   = threadIdx.x;
    const int flat  = blockIdx.x;
    const int b     = flat / BLK_PER_B;              // batch
    const int w64   = flat % BLK_PER_B;              // 0..63 within batch
    const int chunk = w64 % NCHUNK;
    const int cs    = w64 / NCHUNK;

    const int  t4    = chunk * T_PER_BLK + tid * 4;
    const bool valid = (t4 < T_DIM);

    const size_t xbase = ((size_t)b * C_DIM + cs * CPS) * T_DIM + t4;

    // ================= Phase 1: partial channel reduction =================
    if (valid) {
        const float* px = x + xbase;
        float4 s = make_float4(0.f, 0.f, 0.f, 0.f);
        float4 p = make_float4(0.f, 0.f, 0.f, 0.f);
        #pragma unroll 8
        for (int c = 0; c < CPS; c++) {
            const float4 v = __ldcs((const float4*)(px + (size_t)c * T_DIM));
            s.x += v.x; s.y += v.y; s.z += v.z; s.w += v.w;
            p.x = fmaf(v.x, v.x, p.x); p.y = fmaf(v.y, v.y, p.y);
            p.z = fmaf(v.z, v.z, p.z); p.w = fmaf(v.w, v.w, p.w);
        }
        float2* dst = g_part + ((size_t)cs * B_DIM + b) * T_DIM + t4;
        ((float4*)dst)[0] = make_float4(s.x, p.x, s.y, p.y);   // stays L2-resident
        ((float4*)dst)[1] = make_float4(s.z, p.z, s.w, p.w);
    }
    __syncthreads();
    if (tid == 0) {
        __threadfence();                             // publish partials
        atomicAdd(&done1[b], 1);
    }

    // ================= Phase 2: octant scan (blocks w64 < OCT) =================
    if (w64 < OCT) {
        const int o    = w64;
        const int lane = tid & 31;
        const int wid  = tid >> 5;

        if (tid == 0) wait_counter(&done1[b], BLK_PER_B);
        __syncthreads();

        const float4* p4   = (const float4*)g_part;
        const size_t  strm = (size_t)B_DIM * T_DIM / 2;
        const size_t  base4 = (size_t)b * (T_DIM / 2) + (size_t)o * (OCT_T / 2);

        // combine 4 partial streams (coalesced float4, mostly L2 hits)
        for (int i2 = tid; i2 < OCT_T / 2; i2 += TPB) {
            float4 a0 = p4[base4 + i2];
            const float4 a1 = p4[strm + base4 + i2];
            const float4 a2 = p4[2 * strm + base4 + i2];
            const float4 a3 = p4[3 * strm + base4 + i2];
            a0.x += a1.x + a2.x + a3.x;  a0.y += a1.y + a2.y + a3.y;
            a0.z += a1.z + a2.z + a3.z;  a0.w += a1.w + a2.w + a3.w;
            const int i = i2 * 2;
            sm[SKEW(i)]     = make_float2(a0.x, a0.y);
            sm[SKEW(i + 1)] = make_float2(a0.z, a0.w);
        }
        __syncthreads();

        // blocked local scan, EPT=8 (250 active threads)
        const int start = tid * 8;
        float vs[8], vp[8];
        #pragma unroll
        for (int j = 0; j < 8; j++) {
            const int i = start + j;
            const float2 v = (i < OCT_T) ? sm[SKEW(i)] : make_float2(0.f, 0.f);
            vs[j] = v.x; vp[j] = v.y;
        }
        #pragma unroll
        for (int j = 1; j < 8; j++) { vs[j] += vs[j - 1]; vp[j] += vp[j - 1]; }

        float tS = vs[7], tP = vp[7];
        float iS = tS, iP = tP;
        #pragma unroll
        for (int off = 1; off < 32; off <<= 1) {
            float nS = __shfl_up_sync(0xffffffffu, iS, off);
            float nP = __shfl_up_sync(0xffffffffu, iP, off);
            if (lane >= off) { iS += nS; iP += nP; }
        }
        if (lane == 31) { swS[wid] = iS; swP[wid] = iP; }
        __syncthreads();
        if (wid == 0 && lane < 8) {
            float wS = swS[lane], wP = swP[lane];
            #pragma unroll
            for (int off = 1; off < 8; off <<= 1) {
                float nS = __shfl_up_sync(0xffu, wS, off);
                float nP = __shfl_up_sync(0xffu, wP, off);
                if (lane >= off) { wS += nS; wP += nP; }
            }
            swS[lane] = wS - swS[lane];              // exclusive warp offsets
            swP[lane] = wP - swP[lane];
        }
        __syncthreads();
        const float excS = swS[wid] + (iS - tS);
        const float excP = swP[wid] + (iP - tP);

        // write octant-local inclusive scan (float4 = 2 timesteps)
        if (start < OCT_T) {
            float4* sc4 = (float4*)g_scan;
            #pragma unroll
            for (int k = 0; k < 4; k++) {
                sc4[base4 + start / 2 + k] =
                    make_float4(excS + vs[2 * k],     excP + vp[2 * k],
                                excS + vs[2 * k + 1], excP + vp[2 * k + 1]);
            }
            if (start + 8 == OCT_T)                  // tid 249 owns the octant total
                g_agg[b * OCT + o] = make_float2(excS + vs[7], excP + vp[7]);
        }
        __syncthreads();
        if (tid == 0) {
            __threadfence();                         // publish scan results
            atomicAdd(&done2[b], 1);
        }
    }

    // ================= Phase 3: normalize =================
    if (tid == 0) wait_counter(&done2[b], OCT);
    __syncthreads();

    if (valid) {
        // octant offset folded inline (g_agg is 2 KB -> L1/L2-hot)
        const int oct = t4 / OCT_T;
        float offS = 0.f, offP = 0.f;
        for (int o2 = 0; o2 < oct; o2++) {
            const float2 a = __ldg(&g_agg[b * OCT + o2]);
            offS += a.x; offP += a.y;
        }

        const float4* sp = (const float4*)(g_scan + (size_t)b * T_DIM + t4);
        const float4 l01 = sp[0];
        const float4 l23 = sp[1];

        float mean[4], inv[4];
        {
            const float S[4] = { l01.x, l01.z, l23.x, l23.z };
            const float P[4] = { l01.y, l01.w, l23.y, l23.w };
            #pragma unroll
            for (int j = 0; j < 4; j++) {
                const float cnt = (float)(t4 + 1 + j) * (float)C_DIM;
                const float rc  = __fdividef(1.0f, cnt);
                const float m   = (offS + S[j]) * rc;
                mean[j] = m;
                inv[j]  = rsqrtf((offP + P[j]) * rc - m * m + EPS);
            }
        }

        const int c0 = cs * CPS;
        const float* px = x   + xbase;
        float*       po = out + xbase;
        #pragma unroll 8
        for (int c = 0; c < CPS; c++) {
            const float g  = __ldg(gain + c0 + c);
            const float bi = __ldg(bias + c0 + c);
            const float4 v = __ldcs((const float4*)(px + (size_t)c * T_DIM));
            float4 o;
            o.x = fmaf((v.x - mean[0]) * inv[0], g, bi);
            o.y = fmaf((v.y - mean[1]) * inv[1], g, bi);
            o.z = fmaf((v.z - mean[2]) * inv[2], g, bi);
            o.w = fmaf((v.w - mean[3]) * inv[3], g, bi);
            __stcs((float4*)(po + (size_t)c * T_DIM), o);
        }
    }

    // ---- self-resetting counters (graph-replay safe) ----
    __syncthreads();
    if (tid == 0) {
        const int old = atomicAdd(&done3[b], 1);
        if (old == BLK_PER_B - 1) {                  // last block of this batch
            done1[b] = 0;
            done2[b] = 0;
            __threadfence();
            done3[b] = 0;
        }
    }
}

extern "C" void kernel_launch(void* const* d_in, const int* in_sizes, int n_in,
                              void* d_out, int out_size)
{
    const float* x    = (const float*)d_in[0];
    const float* gain = (const float*)d_in[1];
    const float* bias = (const float*)d_in[2];
    float* out = (float*)d_out;

    cln_fused_kernel<<<GRID_TOTAL, TPB>>>(x, gain, bias, out);
}

// round 17
// speedup vs baseline: 1.7846x; 1.0263x over previous
#include <cuda_runtime.h>
#include <cuda_bf16.h>
#include <cstdint>

// Problem constants (fixed by the dataset): input [B, C, T] fp32
#define B_DIM 16
#define C_DIM 256
#define T_DIM 16000
#define EPS 1e-8f

#define TPB 256
#define T_PER_BLK 1024                 // 256 threads x 4 t (float4)
#define NCHUNK ((T_DIM + T_PER_BLK - 1) / T_PER_BLK)   // 16
#define C_SPLIT 4                      // channel splits (64 channels per block)
#define CPS (C_DIM / C_SPLIT)          // 64
#define BLK_PER_B (NCHUNK * C_SPLIT)   // 64 blocks per batch

#define GRID_TOTAL (BLK_PER_B * B_DIM) // 1024 blocks — co-resident @7/SM (1036 slots)

// scratch (device globals; allocation is forbidden)
__device__ float2 g_part[C_SPLIT * B_DIM * T_DIM];  // per-(cs,b,t) partial (S,P)  8 MB
__device__ float2 g_cagg[B_DIM][NCHUNK][C_SPLIT];   // chunk x cs aggregates (2 KB)
__device__ int    done1[B_DIM][NCHUNK];             // phase-1 arrivals (target 4)
__device__ int    done3[B_DIM];                     // finish arrivals (target 64) -> reset

__global__ __launch_bounds__(TPB, 7) void cln_fused_kernel(
    const float* __restrict__ x,
    const float* __restrict__ gain,
    const float* __restrict__ bias,
    float* __restrict__ out)
{
    __shared__ float swS[8], swP[8];
    __shared__ float s_offS, s_offP;

    const int tid   = threadIdx.x;
    const int lane  = tid & 31;
    const int wid   = tid >> 5;
    const int flat  = blockIdx.x;
    const int b     = flat / BLK_PER_B;
    const int w64   = flat % BLK_PER_B;
    const int chunk = w64 % NCHUNK;
    const int cs    = w64 / NCHUNK;

    const int  t4    = chunk * T_PER_BLK + tid * 4;
    const bool valid = (t4 < T_DIM);

    const size_t xbase = ((size_t)b * C_DIM + cs * CPS) * T_DIM + t4;

    // ================= Phase 1: partial channel reduction =================
    float4 s = make_float4(0.f, 0.f, 0.f, 0.f);
    float4 p = make_float4(0.f, 0.f, 0.f, 0.f);
    if (valid) {
        const float* px = x + xbase;
        #pragma unroll 8
        for (int c = 0; c < CPS; c++) {
            const float4 v = __ldcs((const float4*)(px + (size_t)c * T_DIM));
            s.x += v.x; s.y += v.y; s.z += v.z; s.w += v.w;
            p.x = fmaf(v.x, v.x, p.x); p.y = fmaf(v.y, v.y, p.y);
            p.z = fmaf(v.z, v.z, p.z); p.w = fmaf(v.w, v.w, p.w);
        }
        float2* dst = g_part + ((size_t)cs * B_DIM + b) * T_DIM + t4;
        ((float4*)dst)[0] = make_float4(s.x, p.x, s.y, p.y);   // L2-resident
        ((float4*)dst)[1] = make_float4(s.z, p.z, s.w, p.w);
    }

    // block aggregate of (S, P) for this (b, chunk, cs)
    {
        float ts = s.x + s.y + s.z + s.w;
        float tp = p.x + p.y + p.z + p.w;
        #pragma unroll
        for (int off = 16; off; off >>= 1) {
            ts += __shfl_xor_sync(0xffffffffu, ts, off);
            tp += __shfl_xor_sync(0xffffffffu, tp, off);
        }
        if (lane == 0) { swS[wid] = ts; swP[wid] = tp; }
        __syncthreads();
        if (wid == 0 && lane < 8) {
            float aS = swS[lane], aP = swP[lane];
            #pragma unroll
            for (int off = 4; off; off >>= 1) {
                aS += __shfl_xor_sync(0xffu, aS, off);
                aP += __shfl_xor_sync(0xffu, aP, off);
            }
            if (lane == 0) g_cagg[b][chunk][cs] = make_float2(aS, aP);
        }
    }
    __threadfence();                                  // publish g_part + g_cagg
    __syncthreads();
    if (tid == 0) atomicAdd(&done1[b][chunk], 1);

    // ================= Wait: chunks 0..chunk of this batch complete =================
    if (tid == 0) {
        volatile int* d1 = &done1[b][0];
        for (int c2 = 0; c2 <= chunk; c2++)
            while (d1[c2] < C_SPLIT) { __nanosleep(64); }
        __threadfence();                              // acquire producers' writes
        // fold preceding-chunk aggregates (<= 60 L1-hot loads)
        float offS = 0.f, offP = 0.f;
        for (int c2 = 0; c2 < chunk; c2++) {
            #pragma unroll
            for (int k = 0; k < C_SPLIT; k++) {
                const float2 a = g_cagg[b][c2][k];
                offS += a.x; offP += a.y;
            }
        }
        s_offS = offS; s_offP = offP;
    }
    __syncthreads();

    // ================= Own-chunk scan (in registers, all blocks in parallel) =========
    float vs[4], vp[4];
    {
        float4 e01 = make_float4(0.f, 0.f, 0.f, 0.f);   // {S0,P0,S1,P1}
        float4 e23 = make_float4(0.f, 0.f, 0.f, 0.f);
        if (valid) {
            const size_t strm = (size_t)B_DIM * T_DIM / 2;   // float4s per cs stream
            const size_t i4   = (size_t)b * (T_DIM / 2) + t4 / 2;
            const float4* p4  = (const float4*)g_part;
            #pragma unroll
            for (int k = 0; k < C_SPLIT; k++) {
                const float4 a = p4[k * strm + i4];
                const float4 c = p4[k * strm + i4 + 1];
                e01.x += a.x; e01.y += a.y; e01.z += a.z; e01.w += a.w;
                e23.x += c.x; e23.y += c.y; e23.z += c.z; e23.w += c.w;
            }
        }
        vs[0] = e01.x;          vp[0] = e01.y;
        vs[1] = vs[0] + e01.z;  vp[1] = vp[0] + e01.w;
        vs[2] = vs[1] + e23.x;  vp[2] = vp[1] + e23.y;
        vs[3] = vs[2] + e23.z;  vp[3] = vp[2] + e23.w;
    }
    {
        float iS = vs[3], iP = vp[3];
        #pragma unroll
        for (int off = 1; off < 32; off <<= 1) {
            const float nS = __shfl_up_sync(0xffffffffu, iS, off);
            const float nP = __shfl_up_sync(0xffffffffu, iP, off);
            if (lane >= off) { iS += nS; iP += nP; }
        }
        if (lane == 31) { swS[wid] = iS; swP[wid] = iP; }
        __syncthreads();
        if (wid == 0 && lane < 8) {
            float wS = swS[lane], wP = swP[lane];
            #pragma unroll
            for (int off = 1; off < 8; off <<= 1) {
                const float nS = __shfl_up_sync(0xffu, wS, off);
                const float nP = __shfl_up_sync(0xffu, wP, off);
                if (lane >= off) { wS += nS; wP += nP; }
            }
            swS[lane] = wS - swS[lane];               // exclusive warp offsets
            swP[lane] = wP - swP[lane];
        }
        __syncthreads();
        const float excS = swS[wid] + (iS - vs[3]) + s_offS;
        const float excP = swP[wid] + (iP - vp[3]) + s_offP;
        #pragma unroll
        for (int j = 0; j < 4; j++) { vs[j] += excS; vp[j] += excP; }
    }

    // ================= Phase 3: normalize =================
    if (valid) {
        float mean[4], inv[4];
        #pragma unroll
        for (int j = 0; j < 4; j++) {
            const float cnt = (float)(t4 + 1 + j) * (float)C_DIM;
            const float rc  = __fdividef(1.0f, cnt);
            const float m   = vs[j] * rc;
            mean[j] = m;
            inv[j]  = rsqrtf(vp[j] * rc - m * m + EPS);
        }

        const int c0 = cs * CPS;
        const float* px = x   + xbase;
        float*       po = out + xbase;
        #pragma unroll 8
        for (int c = 0; c < CPS; c++) {
            const float g  = __ldg(gain + c0 + c);
            const float bi = __ldg(bias + c0 + c);
            const float4 v = __ldcs((const float4*)(px + (size_t)c * T_DIM));
            float4 o;
            o.x = fmaf((v.x - mean[0]) * inv[0], g, bi);
            o.y = fmaf((v.y - mean[1]) * inv[1], g, bi);
            o.z = fmaf((v.z - mean[2]) * inv[2], g, bi);
            o.w = fmaf((v.w - mean[3]) * inv[3], g, bi);
            __stcs((float4*)(po + (size_t)c * T_DIM), o);
        }
    }

    // ---- self-resetting counters (graph-replay safe) ----
    __syncthreads();
    if (tid == 0) {
        const int old = atomicAdd(&done3[b], 1);
        if (old == BLK_PER_B - 1) {                   // last block of this batch
            #pragma unroll
            for (int c2 = 0; c2 < NCHUNK; c2++) done1[b][c2] = 0;
            __threadfence();
            done3[b] = 0;
        }
    }
}

extern "C" void kernel_launch(void* const* d_in, const int* in_sizes, int n_in,
                              void* d_out, int out_size)
{
    const float* x    = (const float*)d_in[0];
    const float* gain = (const float*)d_in[1];
    const float* bias = (const float*)d_in[2];
    float* out = (float*)d_out;

    cln_fused_kernel<<<GRID_TOTAL, TPB>>>(x, gain, bias, out);
}